// round 14
// baseline (speedup 1.0000x reference)
#include <cuda_runtime.h>
#include <cuda_fp16.h>
#include <math.h>
#include <stdint.h>

#define BB 128
#define MM 64
#define DD 512
#define KK 4096
#define CC 64

// ---------------------------------------------------------------------------
// scratch (__device__ globals per allocation-free rule)
// ---------------------------------------------------------------------------
__device__ __align__(16) __half g_Ch[KK*DD];      // C, f16, class-sorted rows
__device__ int     g_rank[KK];
__device__ uint8_t g_clsSorted[KK];
__device__ float   g_evi[BB*MM*CC];

// ---------------------------------------------------------------------------
__device__ __forceinline__ uint32_t smem_to_u32(const void* p) {
    uint32_t a;
    asm("{ .reg .u64 t; cvta.to.shared.u64 t, %1; cvt.u32.u64 %0, t; }" : "=r"(a) : "l"(p));
    return a;
}
__device__ __forceinline__ void cp16(uint32_t dst, const void* src) {
    asm volatile("cp.async.cg.shared.global [%0], [%1], 16;" :: "r"(dst), "l"(src));
}
__device__ __forceinline__ void cp_commit() { asm volatile("cp.async.commit_group;" ::: "memory"); }
__device__ __forceinline__ void cp_wait0()  { asm volatile("cp.async.wait_group 0;" ::: "memory"); }
__device__ __forceinline__ void cp_wait1()  { asm volatile("cp.async.wait_group 1;" ::: "memory"); }

__device__ __forceinline__ void ldm_x4(uint32_t r[4], uint32_t addr) {
    asm volatile("ldmatrix.sync.aligned.m8n8.x4.shared.b16 {%0,%1,%2,%3}, [%4];"
        : "=r"(r[0]), "=r"(r[1]), "=r"(r[2]), "=r"(r[3]) : "r"(addr));
}
__device__ __forceinline__ void mma16816(float* c, const uint32_t* a, uint32_t b0, uint32_t b1) {
    asm volatile(
        "mma.sync.aligned.m16n8k16.row.col.f32.f16.f16.f32 "
        "{%0,%1,%2,%3}, {%4,%5,%6,%7}, {%8,%9}, {%0,%1,%2,%3};"
        : "+f"(c[0]), "+f"(c[1]), "+f"(c[2]), "+f"(c[3])
        : "r"(a[0]), "r"(a[1]), "r"(a[2]), "r"(a[3]), "r"(b0), "r"(b1));
}

// warp-0 reduction over red[64] (sum if OPSUM, else max) -> sc[slot]
template <bool OPSUM>
__device__ __forceinline__ void w0_reduce(const float* red, float* sc, int slot,
                                          int wid, int lane) {
    if (wid == 0) {
        float v0 = red[lane], v1 = red[lane + 32];
        float v = OPSUM ? (v0 + v1) : fmaxf(v0, v1);
        #pragma unroll
        for (int o = 16; o > 0; o >>= 1) {
            float t = __shfl_xor_sync(0xffffffffu, v, o);
            v = OPSUM ? (v + t) : fmaxf(v, t);
        }
        if (lane == 0) sc[slot] = v;
    }
}

// ---------------------------------------------------------------------------
// k_perm: deterministic stable class-sort ranks (grid 64, block 256, 4-way)
// ---------------------------------------------------------------------------
__global__ void k_perm(const int* __restrict__ Ccls) {
    __shared__ int cls_s[KK];
    __shared__ int partial[64][4];
    int tid = threadIdx.x;
    for (int i = tid; i < KK; i += 256) cls_s[i] = Ccls[i] & 63;
    __syncthreads();
    int li = tid >> 2, qt = tid & 3;
    int i = blockIdx.x * 64 + li;
    int ci = cls_s[i];
    int cnt = 0;
    for (int j = qt*1024; j < qt*1024 + 1024; j++) {
        int cj = cls_s[j];
        cnt += (cj < ci) || (cj == ci && j < i);
    }
    partial[li][qt] = cnt;
    __syncthreads();
    if (qt == 0) {
        int rank = partial[li][0] + partial[li][1] + partial[li][2] + partial[li][3];
        g_rank[i] = rank;
        g_clsSorted[rank] = (uint8_t)ci;
    }
}

// prep_C: fp32 -> f16, scatter rows to class-sorted positions
__global__ void prep_C(const float* __restrict__ Cmat) {
    long i = (long)blockIdx.x * 256 + threadIdx.x;      // over float4s
    int row = (int)(i >> 7), col4 = (int)(i & 127);
    float4 v = ((const float4*)Cmat)[i];
    int r = g_rank[row];
    __half2 h0 = __floats2half2_rn(v.x, v.y);
    __half2 h1 = __floats2half2_rn(v.z, v.w);
    uint2 u; u.x = *(uint32_t*)&h0; u.y = *(uint32_t*)&h1;
    ((uint2*)(g_Ch + (size_t)r * DD))[col4] = u;
}

// ---------------------------------------------------------------------------
// K2: f16 HMMA GEMM + class exp-sum. 256 threads (8 warps), 1 CTA/SM.
// CTA = (batch-pair bp = bx>>1, proto-half = bx&1).
// A (128x512 f16, 2 batches, normalized in-kernel) resident.
// B: 2048 protos as 8 tiles of 256 x 8 chunks of 64 k.
// Warps 1(m) x 8(n); warp tile 128m x 32n. Each warp cp.asyncs ONLY its own
// 32 B-rows (exclusive, private double buffer) -> no CTA barrier in the
// chunk loop; ONE barrier per 256-proto tile for the class combine.
// ---------------------------------------------------------------------------
#define THREADS 256
#define ASTR_B  1040u       // A row stride bytes (520 f16)
#define BSTR_B  144u        // B row stride bytes (72 f16, 64k chunk)
#define OFF_A   0u          // 128 x 1040 = 133120
#define OFF_B   133120u     // 8 warps x 2 stages x 4608 = 73728
#define W_BUF   9216u
#define B_STG   4608u       // 32 rows x 144
#define OFF_PART 206848u    // 2 x 128 x 8 f32 = 8192
#define SMEM_EVI 215040

// chunk q: nt = q>>3 (256-proto tile), dc = q&7 (64-k chunk)
// per-warp exclusive: 32 rows x 64 k = 4 KB = 8 cp16/lane
__device__ __forceinline__ void load_Bwarp(uint32_t base, int half, int q,
                                           int wid, int lane) {
    const int nt = q >> 3, dc = q & 7;
    const __half* src0 = g_Ch + (size_t)(half*2048 + nt*256 + wid*32)*DD + dc*64;
    int n0 = lane >> 3, g = lane & 7;
    #pragma unroll
    for (int ii = 0; ii < 8; ii++) {
        int n = n0 + ii*4;
        cp16(base + (uint32_t)n*BSTR_B + (uint32_t)g*16, src0 + (size_t)n*DD + g*8);
    }
}

__global__ void __launch_bounds__(THREADS, 1)
k_evi(const float* __restrict__ feats) {
    extern __shared__ __align__(1024) char smem[];
    uint32_t smem_base = smem_to_u32(smem);
    const int tid = threadIdx.x, wid = tid >> 5, lane = tid & 31;
    const int bp = blockIdx.x >> 1, half = blockIdx.x & 1;

    float* part = (float*)(smem + OFF_PART);   // [2][128][8]

    const uint32_t wB = smem_base + OFF_B + (uint32_t)wid*W_BUF;

    // start this warp's B chunk 0
    load_Bwarp(wB, half, 0, wid, lane);
    cp_commit();

    // A fill: normalize 128 rows (batches 2bp, 2bp+1) fp32 -> f16, stride 520
    {
        const float* fb = feats + (size_t)(bp*2)*MM*DD;
        for (int rr = 0; rr < 16; rr++) {
            int row = wid*16 + rr;
            const float4* rp = (const float4*)(fb + (size_t)row*DD);
            float4 v[4]; float ss = 0.f;
            #pragma unroll
            for (int u = 0; u < 4; u++) {
                v[u] = rp[lane + u*32];
                ss += v[u].x*v[u].x + v[u].y*v[u].y + v[u].z*v[u].z + v[u].w*v[u].w;
            }
            #pragma unroll
            for (int o = 16; o > 0; o >>= 1) ss += __shfl_xor_sync(0xffffffffu, ss, o);
            float inv = 1.0f / fmaxf(sqrtf(ss), 1e-12f);
            #pragma unroll
            for (int u = 0; u < 4; u++) {
                __half2 h0 = __floats2half2_rn(v[u].x*inv, v[u].y*inv);
                __half2 h1 = __floats2half2_rn(v[u].z*inv, v[u].w*inv);
                uint2 w; w.x = *(uint32_t*)&h0; w.y = *(uint32_t*)&h1;
                *(uint2*)(smem + OFF_A + (uint32_t)row*ASTR_B + (uint32_t)(lane + u*32)*8) = w;
            }
        }
    }
    __syncthreads();    // A visible to all warps

    const uint32_t aBase = smem_base + OFF_A
        + (uint32_t)(lane & 15)*ASTR_B + (uint32_t)(lane >> 4)*16;
    const uint32_t bLane = (uint32_t)((lane & 7) + ((lane >> 4) << 3))*BSTR_B
        + (uint32_t)((lane >> 3) & 1)*16;

    float acc[8][4][4];

    #pragma unroll 1
    for (int q = 0; q < 64; ++q) {
        const int nt = q >> 3, dc = q & 7;

        if (q + 1 < 64) {
            load_Bwarp(wB + (uint32_t)((q+1) & 1)*B_STG, half, q + 1, wid, lane);
            cp_commit();
            cp_wait1();
        } else {
            cp_wait0();
        }
        __syncwarp();

        if (dc == 0) {
            #pragma unroll
            for (int i = 0; i < 8; i++)
                #pragma unroll
                for (int j = 0; j < 4; j++)
                    #pragma unroll
                    for (int v = 0; v < 4; v++) acc[i][j][v] = 0.f;
        }

        const uint32_t bBuf = wB + (uint32_t)(q & 1)*B_STG + bLane;
        #pragma unroll
        for (int ks = 0; ks < 4; ++ks) {
            uint32_t kb = (uint32_t)(dc*64 + ks*16)*2;
            uint32_t a[8][4];
            #pragma unroll
            for (int i = 0; i < 8; i++) ldm_x4(a[i], aBase + (uint32_t)(i*16)*ASTR_B + kb);
            uint32_t bf[2][4];
            uint32_t bAddr = bBuf + (uint32_t)ks*32;
            ldm_x4(bf[0], bAddr);
            ldm_x4(bf[1], bAddr + 16*BSTR_B);
            #pragma unroll
            for (int i = 0; i < 8; i++) {
                mma16816(acc[i][0], a[i], bf[0][0], bf[0][1]);
                mma16816(acc[i][1], a[i], bf[0][2], bf[0][3]);
                mma16816(acc[i][2], a[i], bf[1][0], bf[1][1]);
                mma16816(acc[i][3], a[i], bf[1][2], bf[1][3]);
            }
        }

        if (dc == 7) {
            // exp + row-sum over this warp's 32 protos (half a class)
            float* pb = part + (nt & 1)*128*8;
            #pragma unroll
            for (int i = 0; i < 8; i++) {
                #pragma unroll
                for (int h = 0; h < 2; h++) {
                    float s = 0.f;
                    #pragma unroll
                    for (int j = 0; j < 4; j++) {
                        s += __expf(2.0f * acc[i][j][h*2 + 0]);
                        s += __expf(2.0f * acc[i][j][h*2 + 1]);
                    }
                    s += __shfl_xor_sync(0xffffffffu, s, 1);
                    s += __shfl_xor_sync(0xffffffffu, s, 2);
                    if ((lane & 3) == 0) {
                        int row = i*16 + h*8 + (lane >> 2);
                        pb[row*8 + wid] = s;
                    }
                }
            }
            __syncthreads();   // once per 256-proto tile (8 per kernel)
            {
                int row = tid >> 1, cg = tid & 1;    // 2 classes per thread
                int batch = bp*2 + (row >> 6), slot = row & 63;
                float* dst = g_evi + ((size_t)batch*MM + slot)*CC;
                #pragma unroll
                for (int cj = 0; cj < 2; ++cj) {
                    int ci = cg*2 + cj;
                    float s = pb[row*8 + ci*2] + pb[row*8 + ci*2 + 1];
                    int c = (int)g_clsSorted[half*2048 + nt*256 + ci*64];
                    dst[c] = 0.5f * logf(fmaxf(s, 1e-8f));
                }
            }
        }
    }
}

// ---------------------------------------------------------------------------
// K3: fused epilogue per batch, latency-parallelized.
// ---------------------------------------------------------------------------
#define KO_S    0u          // S_norm f16 [64][520] = 66560
#define KO_G    66560u      // gathered top1 rows f16 [64][520] = 66560
#define KO_EVI  133120u     // f32 [4096] = 16384
#define KO_SUP  149504u     // f32 [64][68] = 17408
#define KO_W    166912u     // f32 [64]
#define KO_LP   167168u
#define KO_T1V  167424u
#define KO_T1I  167680u     // int [64]
#define KO_SV   167936u     // f32 [64]
#define KO_RED  168192u     // f32 [64]
#define KO_SC   168448u     // f32 [8] scalars + topi
#define KO_SMEM 168480

__global__ void __launch_bounds__(256, 1)
k_out(const float* __restrict__ S_slots,
      const float* __restrict__ slot_prob,
      const float* __restrict__ slot_mask,
      const float* __restrict__ alpha,
      float* __restrict__ out) {
    extern __shared__ __align__(1024) char smem[];
    uint32_t smem_base = smem_to_u32(smem);
    float* evi_s = (float*)(smem + KO_EVI);
    float* sup_s = (float*)(smem + KO_SUP);
    float* w_s   = (float*)(smem + KO_W);
    float* lp_s  = (float*)(smem + KO_LP);
    float* t1v   = (float*)(smem + KO_T1V);
    int*   t1i   = (int*)(smem + KO_T1I);
    float* sv    = (float*)(smem + KO_SV);
    float* red   = (float*)(smem + KO_RED);
    float* sc    = (float*)(smem + KO_SC);
    int*   topi  = (int*)(smem + KO_SC + 24);

    int b = blockIdx.x, tid = threadIdx.x;
    int wid = tid >> 5, lane = tid & 31;
    int m = tid & 63;

    // ---- soft-topk weights + log(P_sup), warp-parallel reductions ----
    float mask = slot_mask[m];
    float pv = slot_prob[b*MM + m] * mask;
    sv[m] = pv;
    __syncthreads();
    // top-3 via warp-0 argmax (3 rounds)
    if (wid == 0) {
        float v0 = sv[lane], v1 = sv[lane + 32];
        #pragma unroll 1
        for (int t = 0; t < 3; t++) {
            float bv = v0; int bi = lane;
            if (v1 > bv) { bv = v1; bi = lane + 32; }
            #pragma unroll
            for (int o = 16; o > 0; o >>= 1) {
                float ov = __shfl_xor_sync(0xffffffffu, bv, o);
                int   oi = __shfl_xor_sync(0xffffffffu, bi, o);
                if (ov > bv || (ov == bv && oi < bi)) { bv = ov; bi = oi; }
            }
            if (lane == 0) topi[t] = bi;
            int bb = __shfl_sync(0xffffffffu, bi, 0);
            if (lane == bb) v0 = -INFINITY;
            if (lane + 32 == bb) v1 = -INFINITY;
        }
    }
    __syncthreads();
    float keep = (m == topi[0] || m == topi[1] || m == topi[2]) ? 1.f : 0.f;
    float q = pv * keep;
    red[m] = q; __syncthreads();
    w0_reduce<true>(red, sc, 0, wid, lane);        // sum(q)
    __syncthreads();
    float z = (q - sc[0]*(1.0f/64.0f)) * 2.0f;
    red[m] = z; __syncthreads();
    w0_reduce<false>(red, sc, 1, wid, lane);       // max(z)
    __syncthreads();
    float e = expf(z - sc[1]);
    red[m] = e; __syncthreads();
    w0_reduce<true>(red, sc, 2, wid, lane);        // sum(e)
    __syncthreads();
    float w = (e / sc[2]) * mask;
    red[m] = w; __syncthreads();
    w0_reduce<true>(red, sc, 3, wid, lane);        // sum(w)
    __syncthreads();
    w = w / fmaxf(sc[3], 1e-8f);
    w_s[m] = w;
    float t = logf(w + 1e-8f) * (1.0f/1.6f);
    red[m] = t; __syncthreads();
    w0_reduce<false>(red, sc, 4, wid, lane);       // max(t)
    __syncthreads();
    float et = expf(t - sc[4]);
    red[m] = et; __syncthreads();
    w0_reduce<true>(red, sc, 5, wid, lane);        // sum(et)
    __syncthreads();
    lp_s[m] = fmaxf(t - sc[4] - logf(sc[5]), -18.420680744f);

    // ---- load evi; normalize S rows -> f16 ----
    for (int i = tid; i < MM*CC; i += 256) evi_s[i] = g_evi[(size_t)b*MM*CC + i];
    {
        const float* sb = S_slots + (size_t)b*MM*DD;
        int row = wid*8;
        for (int rr = 0; rr < 8; rr++, row++) {
            const float4* rp = (const float4*)(sb + (size_t)row*DD);
            float4 v[4]; float ss = 0.f;
            #pragma unroll
            for (int u = 0; u < 4; u++) {
                v[u] = rp[lane + u*32];
                ss += v[u].x*v[u].x + v[u].y*v[u].y + v[u].z*v[u].z + v[u].w*v[u].w;
            }
            #pragma unroll
            for (int o = 16; o > 0; o >>= 1) ss += __shfl_xor_sync(0xffffffffu, ss, o);
            float inv = 1.0f / fmaxf(sqrtf(ss), 1e-12f);
            #pragma unroll
            for (int u = 0; u < 4; u++) {
                __half2 h0 = __floats2half2_rn(v[u].x*inv, v[u].y*inv);
                __half2 h1 = __floats2half2_rn(v[u].z*inv, v[u].w*inv);
                uint2 wv; wv.x = *(uint32_t*)&h0; wv.y = *(uint32_t*)&h1;
                *(uint2*)(smem + KO_S + (uint32_t)row*ASTR_B + (uint32_t)(lane + u*32)*8) = wv;
            }
        }
    }
    __syncthreads();

    // top1 over slots per class: 4 threads per class, 16 m each, shfl combine
    {
        int c = tid >> 2, q4 = tid & 3;
        float best = -INFINITY; int bi = 0;
        #pragma unroll 4
        for (int k = 0; k < 16; k++) {
            int mm = q4*16 + k;
            float scv = evi_s[mm*CC + c] * w_s[mm];
            if (scv > best) { best = scv; bi = mm; }
        }
        #pragma unroll
        for (int o = 1; o < 4; o <<= 1) {
            float ov = __shfl_xor_sync(0xffffffffu, best, o);
            int   oi = __shfl_xor_sync(0xffffffffu, bi, o);
            if (ov > best || (ov == best && oi < bi)) { best = ov; bi = oi; }
        }
        if (q4 == 0) { t1v[c] = best; t1i[c] = bi; }
    }
    __syncthreads();

    // gather top1 rows: G[c] = S_norm[t1i[c]]
    {
        int c = tid >> 2, q4 = tid & 3;
        int src = t1i[c];
        const uint4* sp = (const uint4*)(smem + KO_S + (uint32_t)src*ASTR_B);
        uint4* gp = (uint4*)(smem + KO_G + (uint32_t)c*ASTR_B);
        for (int k = q4; k < 65; k += 4) gp[k] = sp[k];
    }
    __syncthreads();

    // cos GEMM 64x64x512 via HMMA: warps 2(m) x 4(n), warp tile 32m x 16n
    {
        int wr = wid & 1, wc = wid >> 1;
        const uint32_t aBase = smem_base + KO_S
            + (uint32_t)(wr*32 + (lane & 15))*ASTR_B + (uint32_t)(lane >> 4)*16;
        const uint32_t bBase = smem_base + KO_G
            + (uint32_t)(wc*16 + (lane & 7) + ((lane >> 4) << 3))*ASTR_B
            + (uint32_t)((lane >> 3) & 1)*16;
        float acc[2][2][4];
        #pragma unroll
        for (int i = 0; i < 2; i++)
            #pragma unroll
            for (int j = 0; j < 2; j++)
                #pragma unroll
                for (int v = 0; v < 4; v++) acc[i][j][v] = 0.f;
        #pragma unroll 4
        for (int ks = 0; ks < 32; ++ks) {
            uint32_t kb = (uint32_t)ks*32;
            uint32_t a0[4], a1[4], bf[4];
            ldm_x4(a0, aBase + kb);
            ldm_x4(a1, aBase + 16*ASTR_B + kb);
            ldm_x4(bf, bBase + kb);
            mma16816(acc[0][0], a0, bf[0], bf[1]);
            mma16816(acc[0][1], a0, bf[2], bf[3]);
            mma16816(acc[1][0], a1, bf[0], bf[1]);
            mma16816(acc[1][1], a1, bf[2], bf[3]);
        }
        #pragma unroll
        for (int i = 0; i < 2; i++) {
            #pragma unroll
            for (int jj = 0; jj < 2; jj++) {
                int m0 = wr*32 + i*16 + (lane >> 2);
                int c0 = wc*16 + jj*8 + (lane & 3)*2;
                #pragma unroll
                for (int v = 0; v < 4; v++) {
                    int mm = m0 + (v >> 1)*8;
                    int c = c0 + (v & 1);
                    float cosv = fmaxf(acc[i][jj][v], 0.f);
                    float sr = evi_s[mm*CC + c] + lp_s[mm] - cosv;
                    if (mm == t1i[c]) sr = -10000.0f;
                    sup_s[mm*68 + c] = sr;
                }
            }
        }
    }
    __syncthreads();

    // support LSE: 4 threads per class
    {
        int c = tid >> 2, q4 = tid & 3;
        float mx = -INFINITY;
        #pragma unroll 4
        for (int k = 0; k < 16; k++) mx = fmaxf(mx, sup_s[(q4*16 + k)*68 + c]);
        #pragma unroll
        for (int o = 1; o < 4; o <<= 1) mx = fmaxf(mx, __shfl_xor_sync(0xffffffffu, mx, o));
        float sum = 0.f;
        #pragma unroll 4
        for (int k = 0; k < 16; k++) sum += expf(sup_s[(q4*16 + k)*68 + c] - mx);
        #pragma unroll
        for (int o = 1; o < 4; o <<= 1) sum += __shfl_xor_sync(0xffffffffu, sum, o);
        if (q4 == 0) {
            float sval = mx + logf(sum);
            out[b*CC + c] = alpha[0] * (t1v[c] + 0.4f * sval);
        }
    }
}

// ---------------------------------------------------------------------------
extern "C" void kernel_launch(void* const* d_in, const int* in_sizes, int n_in,
                              void* d_out, int out_size) {
    const float* feats     = (const float*)d_in[0];
    const float* slot_prob = (const float*)d_in[1];
    const float* slot_mask = (const float*)d_in[2];
    const float* S_slots   = (const float*)d_in[3];
    const float* Cmat      = (const float*)d_in[4];
    const int*   Ccls      = (const int*)d_in[5];
    const float* alpha     = (const float*)d_in[6];
    float* out = (float*)d_out;

    cudaFuncSetAttribute(k_evi, cudaFuncAttributeMaxDynamicSharedMemorySize, SMEM_EVI);
    cudaFuncSetAttribute(k_out, cudaFuncAttributeMaxDynamicSharedMemorySize, KO_SMEM);

    k_perm<<<KK/64, 256>>>(Ccls);
    prep_C<<<KK*DD/1024, 256>>>(Cmat);
    k_evi<<<BB, THREADS, SMEM_EVI>>>(feats);
    k_out<<<BB, 256, KO_SMEM>>>(S_slots, slot_prob, slot_mask, alpha, out);
}

// round 15
// speedup vs baseline: 1.5219x; 1.5219x over previous
#include <cuda_runtime.h>
#include <cuda_fp16.h>
#include <math.h>
#include <stdint.h>

#define BB 128
#define MM 64
#define DD 512
#define KK 4096
#define CC 64

// ---------------------------------------------------------------------------
// scratch (__device__ globals per allocation-free rule)
// ---------------------------------------------------------------------------
__device__ __align__(16) __half g_Ch[KK*DD];      // C, f16, class-sorted rows
__device__ int     g_rank[KK];
__device__ uint8_t g_clsSorted[KK];
__device__ float   g_evi[BB*MM*CC];

// ---------------------------------------------------------------------------
__device__ __forceinline__ uint32_t smem_to_u32(const void* p) {
    uint32_t a;
    asm("{ .reg .u64 t; cvta.to.shared.u64 t, %1; cvt.u32.u64 %0, t; }" : "=r"(a) : "l"(p));
    return a;
}
__device__ __forceinline__ void cp16(uint32_t dst, const void* src) {
    asm volatile("cp.async.cg.shared.global [%0], [%1], 16;" :: "r"(dst), "l"(src));
}
__device__ __forceinline__ void cp_commit() { asm volatile("cp.async.commit_group;" ::: "memory"); }
__device__ __forceinline__ void cp_wait0()  { asm volatile("cp.async.wait_group 0;" ::: "memory"); }
__device__ __forceinline__ void cp_wait1()  { asm volatile("cp.async.wait_group 1;" ::: "memory"); }

__device__ __forceinline__ void ldm_x4(uint32_t r[4], uint32_t addr) {
    asm volatile("ldmatrix.sync.aligned.m8n8.x4.shared.b16 {%0,%1,%2,%3}, [%4];"
        : "=r"(r[0]), "=r"(r[1]), "=r"(r[2]), "=r"(r[3]) : "r"(addr));
}
__device__ __forceinline__ void mma16816(float* c, const uint32_t* a, uint32_t b0, uint32_t b1) {
    asm volatile(
        "mma.sync.aligned.m16n8k16.row.col.f32.f16.f16.f32 "
        "{%0,%1,%2,%3}, {%4,%5,%6,%7}, {%8,%9}, {%0,%1,%2,%3};"
        : "+f"(c[0]), "+f"(c[1]), "+f"(c[2]), "+f"(c[3])
        : "r"(a[0]), "r"(a[1]), "r"(a[2]), "r"(a[3]), "r"(b0), "r"(b1));
}

// ---------------------------------------------------------------------------
// k_perm: deterministic stable class-sort ranks (grid 64, block 256, 4-way)
// ---------------------------------------------------------------------------
__global__ void k_perm(const int* __restrict__ Ccls) {
    __shared__ int cls_s[KK];
    __shared__ int partial[64][4];
    int tid = threadIdx.x;
    for (int i = tid; i < KK; i += 256) cls_s[i] = Ccls[i] & 63;
    __syncthreads();
    int li = tid >> 2, qt = tid & 3;
    int i = blockIdx.x * 64 + li;
    int ci = cls_s[i];
    int cnt = 0;
    for (int j = qt*1024; j < qt*1024 + 1024; j++) {
        int cj = cls_s[j];
        cnt += (cj < ci) || (cj == ci && j < i);
    }
    partial[li][qt] = cnt;
    __syncthreads();
    if (qt == 0) {
        int rank = partial[li][0] + partial[li][1] + partial[li][2] + partial[li][3];
        g_rank[i] = rank;
        g_clsSorted[rank] = (uint8_t)ci;
    }
}

// prep_C: fp32 -> f16, scatter rows to class-sorted positions
__global__ void prep_C(const float* __restrict__ Cmat) {
    long i = (long)blockIdx.x * 256 + threadIdx.x;      // over float4s
    int row = (int)(i >> 7), col4 = (int)(i & 127);
    float4 v = ((const float4*)Cmat)[i];
    int r = g_rank[row];
    __half2 h0 = __floats2half2_rn(v.x, v.y);
    __half2 h1 = __floats2half2_rn(v.z, v.w);
    uint2 u; u.x = *(uint32_t*)&h0; u.y = *(uint32_t*)&h1;
    ((uint2*)(g_Ch + (size_t)r * DD))[col4] = u;
}

// ---------------------------------------------------------------------------
// K2: f16 HMMA GEMM + class exp-sum. 256 threads (8 warps), 1 CTA/SM.
// CTA = (batch-pair bp = bx>>1, proto-half = bx&1).
// A (128x512 f16, 2 batches, normalized in-kernel) resident.
// B: 2048 protos as 8 tiles of 256 x 16 chunks of 32 k.
// Warps 1(m) x 8(n); warp tile 128m x 32n. Each warp cp.asyncs ONLY its own
// 32 B-rows (exclusive, private double buffer) -> no CTA barrier in the
// chunk loop; ONE barrier per 256-proto tile for the class combine.
// (Exact R12 configuration — verified 150.3us total.)
// ---------------------------------------------------------------------------
#define THREADS 256
#define ASTR_B  1040u       // A row stride bytes (520 f16)
#define BSTR_B  80u         // B row stride bytes (40 f16, 32k chunk)
#define OFF_A   0u          // 128 x 1040 = 133120
#define OFF_B   133120u     // 8 warps x 2 stages x 2560 = 40960
#define W_BUF   5120u
#define B_STG   2560u       // 32 rows x 80
#define OFF_PART 174080u    // 2 x 128 x 8 f32 = 8192
#define SMEM_EVI 182272

// chunk q: nt = q>>4 (256-proto tile), dc = q&15 (32-k chunk)
// per-warp exclusive: 32 rows x 32 k = 2 KB = 4 cp16/lane
__device__ __forceinline__ void load_Bwarp(uint32_t base, int half, int q,
                                           int wid, int lane) {
    const int nt = q >> 4, dc = q & 15;
    const __half* src0 = g_Ch + (size_t)(half*2048 + nt*256 + wid*32)*DD + dc*32;
    int n0 = lane >> 2, g = lane & 3;
    #pragma unroll
    for (int ii = 0; ii < 4; ii++) {
        int n = n0 + ii*8;
        cp16(base + (uint32_t)n*BSTR_B + (uint32_t)g*16, src0 + (size_t)n*DD + g*8);
    }
}

__global__ void __launch_bounds__(THREADS, 1)
k_evi(const float* __restrict__ feats) {
    extern __shared__ __align__(1024) char smem[];
    uint32_t smem_base = smem_to_u32(smem);
    const int tid = threadIdx.x, wid = tid >> 5, lane = tid & 31;
    const int bp = blockIdx.x >> 1, half = blockIdx.x & 1;

    float* part = (float*)(smem + OFF_PART);   // [2][128][8]

    const uint32_t wB = smem_base + OFF_B + (uint32_t)wid*W_BUF;

    // start this warp's B chunk 0
    load_Bwarp(wB, half, 0, wid, lane);
    cp_commit();

    // A fill: normalize 128 rows (batches 2bp, 2bp+1) fp32 -> f16, stride 520
    {
        const float* fb = feats + (size_t)(bp*2)*MM*DD;
        for (int rr = 0; rr < 16; rr++) {
            int row = wid*16 + rr;
            const float4* rp = (const float4*)(fb + (size_t)row*DD);
            float4 v[4]; float ss = 0.f;
            #pragma unroll
            for (int u = 0; u < 4; u++) {
                v[u] = rp[lane + u*32];
                ss += v[u].x*v[u].x + v[u].y*v[u].y + v[u].z*v[u].z + v[u].w*v[u].w;
            }
            #pragma unroll
            for (int o = 16; o > 0; o >>= 1) ss += __shfl_xor_sync(0xffffffffu, ss, o);
            float inv = 1.0f / fmaxf(sqrtf(ss), 1e-12f);
            #pragma unroll
            for (int u = 0; u < 4; u++) {
                __half2 h0 = __floats2half2_rn(v[u].x*inv, v[u].y*inv);
                __half2 h1 = __floats2half2_rn(v[u].z*inv, v[u].w*inv);
                uint2 w; w.x = *(uint32_t*)&h0; w.y = *(uint32_t*)&h1;
                *(uint2*)(smem + OFF_A + (uint32_t)row*ASTR_B + (uint32_t)(lane + u*32)*8) = w;
            }
        }
    }
    __syncthreads();    // A visible to all warps

    const uint32_t aBase = smem_base + OFF_A
        + (uint32_t)(lane & 15)*ASTR_B + (uint32_t)(lane >> 4)*16;
    const uint32_t bLane = (uint32_t)((lane & 7) + ((lane >> 4) << 3))*BSTR_B
        + (uint32_t)((lane >> 3) & 1)*16;

    float acc[8][4][4];

    #pragma unroll 1
    for (int q = 0; q < 128; ++q) {
        const int nt = q >> 4, dc = q & 15;

        if (q + 1 < 128) {
            load_Bwarp(wB + (uint32_t)((q+1) & 1)*B_STG, half, q + 1, wid, lane);
            cp_commit();
            cp_wait1();
        } else {
            cp_wait0();
        }
        __syncwarp();

        if (dc == 0) {
            #pragma unroll
            for (int i = 0; i < 8; i++)
                #pragma unroll
                for (int j = 0; j < 4; j++)
                    #pragma unroll
                    for (int v = 0; v < 4; v++) acc[i][j][v] = 0.f;
        }

        const uint32_t bBuf = wB + (uint32_t)(q & 1)*B_STG + bLane;
        #pragma unroll
        for (int ks = 0; ks < 2; ++ks) {
            uint32_t kb = (uint32_t)(dc*32 + ks*16)*2;
            uint32_t a[8][4];
            #pragma unroll
            for (int i = 0; i < 8; i++) ldm_x4(a[i], aBase + (uint32_t)(i*16)*ASTR_B + kb);
            uint32_t bf[2][4];
            uint32_t bAddr = bBuf + (uint32_t)ks*32;
            ldm_x4(bf[0], bAddr);
            ldm_x4(bf[1], bAddr + 16*BSTR_B);
            #pragma unroll
            for (int i = 0; i < 8; i++) {
                mma16816(acc[i][0], a[i], bf[0][0], bf[0][1]);
                mma16816(acc[i][1], a[i], bf[0][2], bf[0][3]);
                mma16816(acc[i][2], a[i], bf[1][0], bf[1][1]);
                mma16816(acc[i][3], a[i], bf[1][2], bf[1][3]);
            }
        }

        if (dc == 15) {
            // exp + row-sum over this warp's 32 protos (half a class)
            float* pb = part + (nt & 1)*128*8;
            #pragma unroll
            for (int i = 0; i < 8; i++) {
                #pragma unroll
                for (int h = 0; h < 2; h++) {
                    float s = 0.f;
                    #pragma unroll
                    for (int j = 0; j < 4; j++) {
                        s += __expf(2.0f * acc[i][j][h*2 + 0]);
                        s += __expf(2.0f * acc[i][j][h*2 + 1]);
                    }
                    s += __shfl_xor_sync(0xffffffffu, s, 1);
                    s += __shfl_xor_sync(0xffffffffu, s, 2);
                    if ((lane & 3) == 0) {
                        int row = i*16 + h*8 + (lane >> 2);
                        pb[row*8 + wid] = s;
                    }
                }
            }
            __syncthreads();   // once per 256-proto tile (8 per kernel)
            {
                int row = tid >> 1, cg = tid & 1;    // 2 classes per thread
                int batch = bp*2 + (row >> 6), slot = row & 63;
                float* dst = g_evi + ((size_t)batch*MM + slot)*CC;
                #pragma unroll
                for (int cj = 0; cj < 2; ++cj) {
                    int ci = cg*2 + cj;
                    float s = pb[row*8 + ci*2] + pb[row*8 + ci*2 + 1];
                    int c = (int)g_clsSorted[half*2048 + nt*256 + ci*64];
                    dst[c] = 0.5f * logf(fmaxf(s, 1e-8f));
                }
            }
        }
    }
}

// ---------------------------------------------------------------------------
// K3: fused epilogue per batch. Weights section = R12 (serial, proven);
// top1 and support-LSE parallelized 4 threads/class.
// ---------------------------------------------------------------------------
#define KO_S    0u          // S_norm f16 [64][520] = 66560
#define KO_G    66560u      // gathered top1 rows f16 [64][520] = 66560
#define KO_EVI  133120u     // f32 [4096] = 16384
#define KO_SUP  149504u     // f32 [64][68] = 17408
#define KO_W    166912u     // f32 [64]
#define KO_LP   167168u
#define KO_T1V  167424u
#define KO_T1I  167680u     // int [64]
#define KO_SV   167936u     // f32 [64]
#define KO_RED  168192u     // f32 [64]
#define KO_SC   168448u     // f32 scalars + topi
#define KO_SMEM 168480

__global__ void __launch_bounds__(256, 1)
k_out(const float* __restrict__ S_slots,
      const float* __restrict__ slot_prob,
      const float* __restrict__ slot_mask,
      const float* __restrict__ alpha,
      float* __restrict__ out) {
    extern __shared__ __align__(1024) char smem[];
    uint32_t smem_base = smem_to_u32(smem);
    float* evi_s = (float*)(smem + KO_EVI);
    float* sup_s = (float*)(smem + KO_SUP);
    float* w_s   = (float*)(smem + KO_W);
    float* lp_s  = (float*)(smem + KO_LP);
    float* t1v   = (float*)(smem + KO_T1V);
    int*   t1i   = (int*)(smem + KO_T1I);
    float* sv    = (float*)(smem + KO_SV);
    float* red   = (float*)(smem + KO_RED);
    float* sc    = (float*)(smem + KO_SC);
    int*   topi  = (int*)(smem + KO_SC + 24);

    int b = blockIdx.x, tid = threadIdx.x;
    int wid = tid >> 5, lane = tid & 31;
    int m = tid & 63;

    // ---- soft-topk weights + log(P_sup) (serial reductions, R12-proven) ----
    float mask = slot_mask[m];
    float pv = slot_prob[b*MM + m] * mask;
    sv[m] = pv;
    __syncthreads();
    if (tid == 0) {
        for (int t = 0; t < 3; t++) {
            float best = -INFINITY; int bi = 0;
            for (int i = 0; i < MM; i++) if (sv[i] > best) { best = sv[i]; bi = i; }
            topi[t] = bi; sv[bi] = -INFINITY;
        }
    }
    __syncthreads();
    float keep = (m == topi[0] || m == topi[1] || m == topi[2]) ? 1.f : 0.f;
    float q = pv * keep;
    red[m] = q; __syncthreads();
    if (tid == 0) { float s = 0.f; for (int i = 0; i < MM; i++) s += red[i]; sc[0] = s / (float)MM; }
    __syncthreads();
    float z = (q - sc[0]) * 2.0f;
    red[m] = z; __syncthreads();
    if (tid == 0) { float mx = -INFINITY; for (int i = 0; i < MM; i++) mx = fmaxf(mx, red[i]); sc[1] = mx; }
    __syncthreads();
    float e = expf(z - sc[1]);
    red[m] = e; __syncthreads();
    if (tid == 0) { float s = 0.f; for (int i = 0; i < MM; i++) s += red[i]; sc[2] = s; }
    __syncthreads();
    float w = (e / sc[2]) * mask;
    red[m] = w; __syncthreads();
    if (tid == 0) { float s = 0.f; for (int i = 0; i < MM; i++) s += red[i]; sc[3] = s; }
    __syncthreads();
    w = w / fmaxf(sc[3], 1e-8f);
    w_s[m] = w;
    float t = logf(w + 1e-8f) * (1.0f/1.6f);
    red[m] = t; __syncthreads();
    if (tid == 0) { float mx = -INFINITY; for (int i = 0; i < MM; i++) mx = fmaxf(mx, red[i]); sc[4] = mx; }
    __syncthreads();
    float et = expf(t - sc[4]);
    red[m] = et; __syncthreads();
    if (tid == 0) { float s = 0.f; for (int i = 0; i < MM; i++) s += red[i]; sc[5] = s; }
    __syncthreads();
    lp_s[m] = fmaxf(t - sc[4] - logf(sc[5]), -18.420680744f);

    // ---- load evi; normalize S rows -> f16 ----
    for (int i = tid; i < MM*CC; i += 256) evi_s[i] = g_evi[(size_t)b*MM*CC + i];
    {
        const float* sb = S_slots + (size_t)b*MM*DD;
        int row = wid*8;
        for (int rr = 0; rr < 8; rr++, row++) {
            const float4* rp = (const float4*)(sb + (size_t)row*DD);
            float4 v[4]; float ss = 0.f;
            #pragma unroll
            for (int u = 0; u < 4; u++) {
                v[u] = rp[lane + u*32];
                ss += v[u].x*v[u].x + v[u].y*v[u].y + v[u].z*v[u].z + v[u].w*v[u].w;
            }
            #pragma unroll
            for (int o = 16; o > 0; o >>= 1) ss += __shfl_xor_sync(0xffffffffu, ss, o);
            float inv = 1.0f / fmaxf(sqrtf(ss), 1e-12f);
            #pragma unroll
            for (int u = 0; u < 4; u++) {
                __half2 h0 = __floats2half2_rn(v[u].x*inv, v[u].y*inv);
                __half2 h1 = __floats2half2_rn(v[u].z*inv, v[u].w*inv);
                uint2 wv; wv.x = *(uint32_t*)&h0; wv.y = *(uint32_t*)&h1;
                *(uint2*)(smem + KO_S + (uint32_t)row*ASTR_B + (uint32_t)(lane + u*32)*8) = wv;
            }
        }
    }
    __syncthreads();

    // top1 over slots per class: 4 threads per class, 16 m each, shfl combine
    {
        int c = tid >> 2, q4 = tid & 3;
        float best = -INFINITY; int bi = 0;
        #pragma unroll 4
        for (int k = 0; k < 16; k++) {
            int mm = q4*16 + k;
            float scv = evi_s[mm*CC + c] * w_s[mm];
            if (scv > best) { best = scv; bi = mm; }
        }
        #pragma unroll
        for (int o = 1; o < 4; o <<= 1) {
            float ov = __shfl_xor_sync(0xffffffffu, best, o);
            int   oi = __shfl_xor_sync(0xffffffffu, bi, o);
            if (ov > best || (ov == best && oi < bi)) { best = ov; bi = oi; }
        }
        if (q4 == 0) { t1v[c] = best; t1i[c] = bi; }
    }
    __syncthreads();

    // gather top1 rows: G[c] = S_norm[t1i[c]]
    {
        int c = tid >> 2, q4 = tid & 3;
        int src = t1i[c];
        const uint4* sp = (const uint4*)(smem + KO_S + (uint32_t)src*ASTR_B);
        uint4* gp = (uint4*)(smem + KO_G + (uint32_t)c*ASTR_B);
        for (int k = q4; k < 65; k += 4) gp[k] = sp[k];
    }
    __syncthreads();

    // cos GEMM 64x64x512 via HMMA: warps 2(m) x 4(n), warp tile 32m x 16n
    {
        int wr = wid & 1, wc = wid >> 1;
        const uint32_t aBase = smem_base + KO_S
            + (uint32_t)(wr*32 + (lane & 15))*ASTR_B + (uint32_t)(lane >> 4)*16;
        const uint32_t bBase = smem_base + KO_G
            + (uint32_t)(wc*16 + (lane & 7) + ((lane >> 4) << 3))*ASTR_B
            + (uint32_t)((lane >> 3) & 1)*16;
        float acc[2][2][4];
        #pragma unroll
        for (int i = 0; i < 2; i++)
            #pragma unroll
            for (int j = 0; j < 2; j++)
                #pragma unroll
                for (int v = 0; v < 4; v++) acc[i][j][v] = 0.f;
        #pragma unroll 4
        for (int ks = 0; ks < 32; ++ks) {
            uint32_t kb = (uint32_t)ks*32;
            uint32_t a0[4], a1[4], bf[4];
            ldm_x4(a0, aBase + kb);
            ldm_x4(a1, aBase + 16*ASTR_B + kb);
            ldm_x4(bf, bBase + kb);
            mma16816(acc[0][0], a0, bf[0], bf[1]);
            mma16816(acc[0][1], a0, bf[2], bf[3]);
            mma16816(acc[1][0], a1, bf[0], bf[1]);
            mma16816(acc[1][1], a1, bf[2], bf[3]);
        }
        #pragma unroll
        for (int i = 0; i < 2; i++) {
            #pragma unroll
            for (int jj = 0; jj < 2; jj++) {
                int m0 = wr*32 + i*16 + (lane >> 2);
                int c0 = wc*16 + jj*8 + (lane & 3)*2;
                #pragma unroll
                for (int v = 0; v < 4; v++) {
                    int mm = m0 + (v >> 1)*8;
                    int c = c0 + (v & 1);
                    float cosv = fmaxf(acc[i][jj][v], 0.f);
                    float sr = evi_s[mm*CC + c] + lp_s[mm] - cosv;
                    if (mm == t1i[c]) sr = -10000.0f;
                    sup_s[mm*68 + c] = sr;
                }
            }
        }
    }
    __syncthreads();

    // support LSE: 4 threads per class, shfl combine
    {
        int c = tid >> 2, q4 = tid & 3;
        float mx = -INFINITY;
        #pragma unroll 4
        for (int k = 0; k < 16; k++) mx = fmaxf(mx, sup_s[(q4*16 + k)*68 + c]);
        #pragma unroll
        for (int o = 1; o < 4; o <<= 1) mx = fmaxf(mx, __shfl_xor_sync(0xffffffffu, mx, o));
        float sum = 0.f;
        #pragma unroll 4
        for (int k = 0; k < 16; k++) sum += expf(sup_s[(q4*16 + k)*68 + c] - mx);
        #pragma unroll
        for (int o = 1; o < 4; o <<= 1) sum += __shfl_xor_sync(0xffffffffu, sum, o);
        if (q4 == 0) {
            float sval = mx + logf(sum);
            out[b*CC + c] = alpha[0] * (t1v[c] + 0.4f * sval);
        }
    }
}

// ---------------------------------------------------------------------------
extern "C" void kernel_launch(void* const* d_in, const int* in_sizes, int n_in,
                              void* d_out, int out_size) {
    const float* feats     = (const float*)d_in[0];
    const float* slot_prob = (const float*)d_in[1];
    const float* slot_mask = (const float*)d_in[2];
    const float* S_slots   = (const float*)d_in[3];
    const float* Cmat      = (const float*)d_in[4];
    const int*   Ccls      = (const int*)d_in[5];
    const float* alpha     = (const float*)d_in[6];
    float* out = (float*)d_out;

    cudaFuncSetAttribute(k_evi, cudaFuncAttributeMaxDynamicSharedMemorySize, SMEM_EVI);
    cudaFuncSetAttribute(k_out, cudaFuncAttributeMaxDynamicSharedMemorySize, KO_SMEM);

    k_perm<<<KK/64, 256>>>(Ccls);
    prep_C<<<KK*DD/1024, 256>>>(Cmat);
    k_evi<<<BB, THREADS, SMEM_EVI>>>(feats);
    k_out<<<BB, 256, KO_SMEM>>>(S_slots, slot_prob, slot_mask, alpha, out);
}

// round 16
// speedup vs baseline: 1.5375x; 1.0102x over previous
#include <cuda_runtime.h>
#include <cuda_fp16.h>
#include <math.h>
#include <stdint.h>

#define BB 128
#define MM 64
#define DD 512
#define KK 4096
#define CC 64

// ---------------------------------------------------------------------------
// scratch (__device__ globals per allocation-free rule)
// ---------------------------------------------------------------------------
__device__ __align__(16) __half g_Ch[KK*DD];      // C, f16, class-sorted rows
__device__ int     g_rank[KK];
__device__ uint8_t g_clsSorted[KK];
__device__ float   g_evi[BB*MM*CC];

// ---------------------------------------------------------------------------
__device__ __forceinline__ uint32_t smem_to_u32(const void* p) {
    uint32_t a;
    asm("{ .reg .u64 t; cvta.to.shared.u64 t, %1; cvt.u32.u64 %0, t; }" : "=r"(a) : "l"(p));
    return a;
}
__device__ __forceinline__ void cp16(uint32_t dst, const void* src) {
    asm volatile("cp.async.cg.shared.global [%0], [%1], 16;" :: "r"(dst), "l"(src));
}
__device__ __forceinline__ void cp_commit() { asm volatile("cp.async.commit_group;" ::: "memory"); }
__device__ __forceinline__ void cp_wait0()  { asm volatile("cp.async.wait_group 0;" ::: "memory"); }
__device__ __forceinline__ void cp_wait1()  { asm volatile("cp.async.wait_group 1;" ::: "memory"); }
__device__ __forceinline__ void cp_wait2()  { asm volatile("cp.async.wait_group 2;" ::: "memory"); }

__device__ __forceinline__ void ldm_x4(uint32_t r[4], uint32_t addr) {
    asm volatile("ldmatrix.sync.aligned.m8n8.x4.shared.b16 {%0,%1,%2,%3}, [%4];"
        : "=r"(r[0]), "=r"(r[1]), "=r"(r[2]), "=r"(r[3]) : "r"(addr));
}
__device__ __forceinline__ void mma16816(float* c, const uint32_t* a, uint32_t b0, uint32_t b1) {
    asm volatile(
        "mma.sync.aligned.m16n8k16.row.col.f32.f16.f16.f32 "
        "{%0,%1,%2,%3}, {%4,%5,%6,%7}, {%8,%9}, {%0,%1,%2,%3};"
        : "+f"(c[0]), "+f"(c[1]), "+f"(c[2]), "+f"(c[3])
        : "r"(a[0]), "r"(a[1]), "r"(a[2]), "r"(a[3]), "r"(b0), "r"(b1));
}

// full-warp reductions (32 lanes)
__device__ __forceinline__ float wsum32(float v) {
    #pragma unroll
    for (int o = 16; o > 0; o >>= 1) v += __shfl_xor_sync(0xffffffffu, v, o);
    return v;
}
__device__ __forceinline__ float wmax32(float v) {
    #pragma unroll
    for (int o = 16; o > 0; o >>= 1) v = fmaxf(v, __shfl_xor_sync(0xffffffffu, v, o));
    return v;
}

// ---------------------------------------------------------------------------
// k_perm: deterministic stable class-sort ranks (grid 64, block 256, 4-way)
// ---------------------------------------------------------------------------
__global__ void k_perm(const int* __restrict__ Ccls) {
    __shared__ int cls_s[KK];
    __shared__ int partial[64][4];
    int tid = threadIdx.x;
    for (int i = tid; i < KK; i += 256) cls_s[i] = Ccls[i] & 63;
    __syncthreads();
    int li = tid >> 2, qt = tid & 3;
    int i = blockIdx.x * 64 + li;
    int ci = cls_s[i];
    int cnt = 0;
    for (int j = qt*1024; j < qt*1024 + 1024; j++) {
        int cj = cls_s[j];
        cnt += (cj < ci) || (cj == ci && j < i);
    }
    partial[li][qt] = cnt;
    __syncthreads();
    if (qt == 0) {
        int rank = partial[li][0] + partial[li][1] + partial[li][2] + partial[li][3];
        g_rank[i] = rank;
        g_clsSorted[rank] = (uint8_t)ci;
    }
}

// prep_C: fp32 -> f16, scatter rows to class-sorted positions
__global__ void prep_C(const float* __restrict__ Cmat) {
    long i = (long)blockIdx.x * 256 + threadIdx.x;      // over float4s
    int row = (int)(i >> 7), col4 = (int)(i & 127);
    float4 v = ((const float4*)Cmat)[i];
    int r = g_rank[row];
    __half2 h0 = __floats2half2_rn(v.x, v.y);
    __half2 h1 = __floats2half2_rn(v.z, v.w);
    uint2 u; u.x = *(uint32_t*)&h0; u.y = *(uint32_t*)&h1;
    ((uint2*)(g_Ch + (size_t)r * DD))[col4] = u;
}

// ---------------------------------------------------------------------------
// K2: f16 HMMA GEMM + class exp-sum. 256 threads (8 warps), 1 CTA/SM.
// CTA = (batch-pair bp = bx>>1, proto-half = bx&1).
// A (128x512 f16, 2 batches, normalized in-kernel) resident.
// B: 2048 protos as 8 tiles of 256 x 16 chunks of 32 k.
// Warps 1(m) x 8(n); warp tile 128m x 32n. Each warp cp.asyncs ONLY its own
// 32 B-rows (exclusive, private 3-stage buffer) -> no CTA barrier in the
// chunk loop; ONE barrier per 256-proto tile for the class combine.
// ---------------------------------------------------------------------------
#define THREADS 256
#define ASTR_B  1040u       // A row stride bytes (520 f16)
#define BSTR_B  80u         // B row stride bytes (40 f16, 32k chunk)
#define OFF_A   0u          // 128 x 1040 = 133120
#define OFF_B   133120u     // 8 warps x 3 stages x 2560 = 61440
#define W_BUF   7680u
#define B_STG   2560u       // 32 rows x 80
#define OFF_PART 194560u    // 2 x 128 x 8 f32 = 8192
#define SMEM_EVI 202752

// chunk q: nt = q>>4 (256-proto tile), dc = q&15 (32-k chunk)
// per-warp exclusive: 32 rows x 32 k = 2 KB = 4 cp16/lane
__device__ __forceinline__ void load_Bwarp(uint32_t base, int half, int q,
                                           int wid, int lane) {
    const int nt = q >> 4, dc = q & 15;
    const __half* src0 = g_Ch + (size_t)(half*2048 + nt*256 + wid*32)*DD + dc*32;
    int n0 = lane >> 2, g = lane & 3;
    #pragma unroll
    for (int ii = 0; ii < 4; ii++) {
        int n = n0 + ii*8;
        cp16(base + (uint32_t)n*BSTR_B + (uint32_t)g*16, src0 + (size_t)n*DD + g*8);
    }
}

__global__ void __launch_bounds__(THREADS, 1)
k_evi(const float* __restrict__ feats) {
    extern __shared__ __align__(1024) char smem[];
    uint32_t smem_base = smem_to_u32(smem);
    const int tid = threadIdx.x, wid = tid >> 5, lane = tid & 31;
    const int bp = blockIdx.x >> 1, half = blockIdx.x & 1;

    float* part = (float*)(smem + OFF_PART);   // [2][128][8]

    const uint32_t wB = smem_base + OFF_B + (uint32_t)wid*W_BUF;

    // prime 2 stages
    load_Bwarp(wB, half, 0, wid, lane);
    cp_commit();
    load_Bwarp(wB + B_STG, half, 1, wid, lane);
    cp_commit();

    // A fill: normalize 128 rows (batches 2bp, 2bp+1) fp32 -> f16, stride 520
    {
        const float* fb = feats + (size_t)(bp*2)*MM*DD;
        for (int rr = 0; rr < 16; rr++) {
            int row = wid*16 + rr;
            const float4* rp = (const float4*)(fb + (size_t)row*DD);
            float4 v[4]; float ss = 0.f;
            #pragma unroll
            for (int u = 0; u < 4; u++) {
                v[u] = rp[lane + u*32];
                ss += v[u].x*v[u].x + v[u].y*v[u].y + v[u].z*v[u].z + v[u].w*v[u].w;
            }
            ss = wsum32(ss);
            float inv = 1.0f / fmaxf(sqrtf(ss), 1e-12f);
            #pragma unroll
            for (int u = 0; u < 4; u++) {
                __half2 h0 = __floats2half2_rn(v[u].x*inv, v[u].y*inv);
                __half2 h1 = __floats2half2_rn(v[u].z*inv, v[u].w*inv);
                uint2 w; w.x = *(uint32_t*)&h0; w.y = *(uint32_t*)&h1;
                *(uint2*)(smem + OFF_A + (uint32_t)row*ASTR_B + (uint32_t)(lane + u*32)*8) = w;
            }
        }
    }
    __syncthreads();    // A visible to all warps

    const uint32_t aBase = smem_base + OFF_A
        + (uint32_t)(lane & 15)*ASTR_B + (uint32_t)(lane >> 4)*16;
    const uint32_t bLane = (uint32_t)((lane & 7) + ((lane >> 4) << 3))*BSTR_B
        + (uint32_t)((lane >> 3) & 1)*16;

    float acc[8][4][4];
    int bufsel = 0;

    #pragma unroll 1
    for (int q = 0; q < 128; ++q) {
        const int nt = q >> 4, dc = q & 15;

        if (q + 2 < 128) {
            int nb = bufsel + 2; if (nb >= 3) nb -= 3;
            load_Bwarp(wB + (uint32_t)nb*B_STG, half, q + 2, wid, lane);
            cp_commit();
            cp_wait2();
        } else if (q + 1 < 128) {
            cp_wait1();
        } else {
            cp_wait0();
        }
        __syncwarp();

        if (dc == 0) {
            #pragma unroll
            for (int i = 0; i < 8; i++)
                #pragma unroll
                for (int j = 0; j < 4; j++)
                    #pragma unroll
                    for (int v = 0; v < 4; v++) acc[i][j][v] = 0.f;
        }

        const uint32_t bBuf = wB + (uint32_t)bufsel*B_STG + bLane;
        #pragma unroll
        for (int ks = 0; ks < 2; ++ks) {
            uint32_t kb = (uint32_t)(dc*32 + ks*16)*2;
            uint32_t a[8][4];
            #pragma unroll
            for (int i = 0; i < 8; i++) ldm_x4(a[i], aBase + (uint32_t)(i*16)*ASTR_B + kb);
            uint32_t bf[2][4];
            uint32_t bAddr = bBuf + (uint32_t)ks*32;
            ldm_x4(bf[0], bAddr);
            ldm_x4(bf[1], bAddr + 16*BSTR_B);
            #pragma unroll
            for (int i = 0; i < 8; i++) {
                mma16816(acc[i][0], a[i], bf[0][0], bf[0][1]);
                mma16816(acc[i][1], a[i], bf[0][2], bf[0][3]);
                mma16816(acc[i][2], a[i], bf[1][0], bf[1][1]);
                mma16816(acc[i][3], a[i], bf[1][2], bf[1][3]);
            }
        }

        if (dc == 15) {
            // exp + row-sum over this warp's 32 protos (half a class)
            float* pb = part + (nt & 1)*128*8;
            #pragma unroll
            for (int i = 0; i < 8; i++) {
                #pragma unroll
                for (int h = 0; h < 2; h++) {
                    float s = 0.f;
                    #pragma unroll
                    for (int j = 0; j < 4; j++) {
                        s += __expf(2.0f * acc[i][j][h*2 + 0]);
                        s += __expf(2.0f * acc[i][j][h*2 + 1]);
                    }
                    s += __shfl_xor_sync(0xffffffffu, s, 1);
                    s += __shfl_xor_sync(0xffffffffu, s, 2);
                    if ((lane & 3) == 0) {
                        int row = i*16 + h*8 + (lane >> 2);
                        pb[row*8 + wid] = s;
                    }
                }
            }
            __syncthreads();   // once per 256-proto tile (8 per kernel)
            {
                int row = tid >> 1, cg = tid & 1;    // 2 classes per thread
                int batch = bp*2 + (row >> 6), slot = row & 63;
                float* dst = g_evi + ((size_t)batch*MM + slot)*CC;
                #pragma unroll
                for (int cj = 0; cj < 2; ++cj) {
                    int ci = cg*2 + cj;
                    float s = pb[row*8 + ci*2] + pb[row*8 + ci*2 + 1];
                    int c = (int)g_clsSorted[half*2048 + nt*256 + ci*64];
                    dst[c] = 0.5f * logf(fmaxf(s, 1e-8f));
                }
            }
        }
        if (++bufsel == 3) bufsel = 0;
    }
}

// ---------------------------------------------------------------------------
// K3: fused epilogue per batch. Weights computed entirely inside warp 0
// (barrier-free, shuffles) WHILE warps 1-7 load evi + normalize S rows 0-55;
// warp 0 then normalizes rows 56-63. One join barrier.
// ---------------------------------------------------------------------------
#define KO_S    0u          // S_norm f16 [64][520] = 66560
#define KO_G    66560u      // gathered top1 rows f16 [64][520] = 66560
#define KO_EVI  133120u     // f32 [4096] = 16384
#define KO_SUP  149504u     // f32 [64][68] = 17408
#define KO_W    166912u     // f32 [64]
#define KO_LP   167168u
#define KO_T1V  167424u
#define KO_T1I  167680u     // int [64]
#define KO_SMEM 167936

__device__ __forceinline__ void norm_row(const float* sb, char* smem, int row, int lane) {
    const float4* rp = (const float4*)(sb + (size_t)row*DD);
    float4 v[4]; float ss = 0.f;
    #pragma unroll
    for (int u = 0; u < 4; u++) {
        v[u] = rp[lane + u*32];
        ss += v[u].x*v[u].x + v[u].y*v[u].y + v[u].z*v[u].z + v[u].w*v[u].w;
    }
    ss = wsum32(ss);
    float inv = 1.0f / fmaxf(sqrtf(ss), 1e-12f);
    #pragma unroll
    for (int u = 0; u < 4; u++) {
        __half2 h0 = __floats2half2_rn(v[u].x*inv, v[u].y*inv);
        __half2 h1 = __floats2half2_rn(v[u].z*inv, v[u].w*inv);
        uint2 wv; wv.x = *(uint32_t*)&h0; wv.y = *(uint32_t*)&h1;
        *(uint2*)(smem + KO_S + (uint32_t)row*ASTR_B + (uint32_t)(lane + u*32)*8) = wv;
    }
}

__global__ void __launch_bounds__(256, 1)
k_out(const float* __restrict__ S_slots,
      const float* __restrict__ slot_prob,
      const float* __restrict__ slot_mask,
      const float* __restrict__ alpha,
      float* __restrict__ out) {
    extern __shared__ __align__(1024) char smem[];
    uint32_t smem_base = smem_to_u32(smem);
    float* evi_s = (float*)(smem + KO_EVI);
    float* sup_s = (float*)(smem + KO_SUP);
    float* w_s   = (float*)(smem + KO_W);
    float* lp_s  = (float*)(smem + KO_LP);
    float* t1v   = (float*)(smem + KO_T1V);
    int*   t1i   = (int*)(smem + KO_T1I);

    int b = blockIdx.x, tid = threadIdx.x;
    int wid = tid >> 5, lane = tid & 31;
    const float* sb = S_slots + (size_t)b*MM*DD;

    if (wid == 0) {
        // ---- warp-0-only soft-topk weights + log(P_sup), barrier-free ----
        int m0 = lane, m1 = lane + 32;
        float mk0 = slot_mask[m0], mk1 = slot_mask[m1];
        float pv0 = slot_prob[b*MM + m0] * mk0;
        float pv1 = slot_prob[b*MM + m1] * mk1;
        float v0 = pv0, v1 = pv1;
        int top0, top1, top2;
        #pragma unroll
        for (int t = 0; t < 3; t++) {
            float bv = v0; int bi = m0;
            if (v1 > bv) { bv = v1; bi = m1; }
            #pragma unroll
            for (int o = 16; o > 0; o >>= 1) {
                float ov = __shfl_xor_sync(0xffffffffu, bv, o);
                int   oi = __shfl_xor_sync(0xffffffffu, bi, o);
                if (ov > bv || (ov == bv && oi < bi)) { bv = ov; bi = oi; }
            }
            int bb = __shfl_sync(0xffffffffu, bi, 0);
            if (t == 0) top0 = bb; else if (t == 1) top1 = bb; else top2 = bb;
            if (m0 == bb) v0 = -INFINITY;
            if (m1 == bb) v1 = -INFINITY;
        }
        float k0 = (m0 == top0 || m0 == top1 || m0 == top2) ? 1.f : 0.f;
        float k1 = (m1 == top0 || m1 == top1 || m1 == top2) ? 1.f : 0.f;
        float q0 = pv0 * k0, q1 = pv1 * k1;
        float mean = wsum32(q0 + q1) * (1.0f/64.0f);
        float z0 = (q0 - mean) * 2.0f, z1 = (q1 - mean) * 2.0f;
        float zmax = wmax32(fmaxf(z0, z1));
        float e0 = expf(z0 - zmax), e1 = expf(z1 - zmax);
        float zsum = wsum32(e0 + e1);
        float w0 = (e0 / zsum) * mk0, w1 = (e1 / zsum) * mk1;
        float wsum = wsum32(w0 + w1);
        float inw = 1.0f / fmaxf(wsum, 1e-8f);
        w0 *= inw; w1 *= inw;
        w_s[m0] = w0; w_s[m1] = w1;
        float t0 = logf(w0 + 1e-8f) * (1.0f/1.6f);
        float t1 = logf(w1 + 1e-8f) * (1.0f/1.6f);
        float tmax = wmax32(fmaxf(t0, t1));
        float et0 = expf(t0 - tmax), et1 = expf(t1 - tmax);
        float lts = logf(wsum32(et0 + et1));
        lp_s[m0] = fmaxf(t0 - tmax - lts, -18.420680744f);
        lp_s[m1] = fmaxf(t1 - tmax - lts, -18.420680744f);
        // then normalize S rows 56..63
        for (int row = 56; row < 64; row++) norm_row(sb, smem, row, lane);
    } else {
        // ---- warps 1-7: load evi + normalize S rows 0..55 ----
        for (int i = tid - 32; i < MM*CC; i += 224) evi_s[i] = g_evi[(size_t)b*MM*CC + i];
        int r0 = (wid - 1) * 8;
        for (int rr = 0; rr < 8; rr++) norm_row(sb, smem, r0 + rr, lane);
    }
    __syncthreads();

    // top1 over slots per class: 4 threads per class, 16 m each, shfl combine
    {
        int c = tid >> 2, q4 = tid & 3;
        float best = -INFINITY; int bi = 0;
        #pragma unroll 4
        for (int k = 0; k < 16; k++) {
            int mm = q4*16 + k;
            float scv = evi_s[mm*CC + c] * w_s[mm];
            if (scv > best) { best = scv; bi = mm; }
        }
        #pragma unroll
        for (int o = 1; o < 4; o <<= 1) {
            float ov = __shfl_xor_sync(0xffffffffu, best, o);
            int   oi = __shfl_xor_sync(0xffffffffu, bi, o);
            if (ov > best || (ov == best && oi < bi)) { best = ov; bi = oi; }
        }
        if (q4 == 0) { t1v[c] = best; t1i[c] = bi; }
    }
    __syncthreads();

    // gather top1 rows: G[c] = S_norm[t1i[c]]
    {
        int c = tid >> 2, q4 = tid & 3;
        int src = t1i[c];
        const uint4* sp = (const uint4*)(smem + KO_S + (uint32_t)src*ASTR_B);
        uint4* gp = (uint4*)(smem + KO_G + (uint32_t)c*ASTR_B);
        for (int k = q4; k < 65; k += 4) gp[k] = sp[k];
    }
    __syncthreads();

    // cos GEMM 64x64x512 via HMMA: warps 2(m) x 4(n), warp tile 32m x 16n
    {
        int wr = wid & 1, wc = wid >> 1;
        const uint32_t aBase = smem_base + KO_S
            + (uint32_t)(wr*32 + (lane & 15))*ASTR_B + (uint32_t)(lane >> 4)*16;
        const uint32_t bBase = smem_base + KO_G
            + (uint32_t)(wc*16 + (lane & 7) + ((lane >> 4) << 3))*ASTR_B
            + (uint32_t)((lane >> 3) & 1)*16;
        float acc[2][2][4];
        #pragma unroll
        for (int i = 0; i < 2; i++)
            #pragma unroll
            for (int j = 0; j < 2; j++)
                #pragma unroll
                for (int v = 0; v < 4; v++) acc[i][j][v] = 0.f;
        #pragma unroll 4
        for (int ks = 0; ks < 32; ++ks) {
            uint32_t kb = (uint32_t)ks*32;
            uint32_t a0[4], a1[4], bf[4];
            ldm_x4(a0, aBase + kb);
            ldm_x4(a1, aBase + 16*ASTR_B + kb);
            ldm_x4(bf, bBase + kb);
            mma16816(acc[0][0], a0, bf[0], bf[1]);
            mma16816(acc[0][1], a0, bf[2], bf[3]);
            mma16816(acc[1][0], a1, bf[0], bf[1]);
            mma16816(acc[1][1], a1, bf[2], bf[3]);
        }
        #pragma unroll
        for (int i = 0; i < 2; i++) {
            #pragma unroll
            for (int jj = 0; jj < 2; jj++) {
                int mB = wr*32 + i*16 + (lane >> 2);
                int c0 = wc*16 + jj*8 + (lane & 3)*2;
                #pragma unroll
                for (int v = 0; v < 4; v++) {
                    int mm = mB + (v >> 1)*8;
                    int c = c0 + (v & 1);
                    float cosv = fmaxf(acc[i][jj][v], 0.f);
                    float sr = evi_s[mm*CC + c] + lp_s[mm] - cosv;
                    if (mm == t1i[c]) sr = -10000.0f;
                    sup_s[mm*68 + c] = sr;
                }
            }
        }
    }
    __syncthreads();

    // support LSE: 4 threads per class, shfl combine
    {
        int c = tid >> 2, q4 = tid & 3;
        float mx = -INFINITY;
        #pragma unroll 4
        for (int k = 0; k < 16; k++) mx = fmaxf(mx, sup_s[(q4*16 + k)*68 + c]);
        #pragma unroll
        for (int o = 1; o < 4; o <<= 1) mx = fmaxf(mx, __shfl_xor_sync(0xffffffffu, mx, o));
        float sum = 0.f;
        #pragma unroll 4
        for (int k = 0; k < 16; k++) sum += expf(sup_s[(q4*16 + k)*68 + c] - mx);
        #pragma unroll
        for (int o = 1; o < 4; o <<= 1) sum += __shfl_xor_sync(0xffffffffu, sum, o);
        if (q4 == 0) {
            float sval = mx + logf(sum);
            out[b*CC + c] = alpha[0] * (t1v[c] + 0.4f * sval);
        }
    }
}

// ---------------------------------------------------------------------------
extern "C" void kernel_launch(void* const* d_in, const int* in_sizes, int n_in,
                              void* d_out, int out_size) {
    const float* feats     = (const float*)d_in[0];
    const float* slot_prob = (const float*)d_in[1];
    const float* slot_mask = (const float*)d_in[2];
    const float* S_slots   = (const float*)d_in[3];
    const float* Cmat      = (const float*)d_in[4];
    const int*   Ccls      = (const int*)d_in[5];
    const float* alpha     = (const float*)d_in[6];
    float* out = (float*)d_out;

    cudaFuncSetAttribute(k_evi, cudaFuncAttributeMaxDynamicSharedMemorySize, SMEM_EVI);
    cudaFuncSetAttribute(k_out, cudaFuncAttributeMaxDynamicSharedMemorySize, KO_SMEM);

    k_perm<<<KK/64, 256>>>(Ccls);
    prep_C<<<KK*DD/1024, 256>>>(Cmat);
    k_evi<<<BB, THREADS, SMEM_EVI>>>(feats);
    k_out<<<BB, 256, KO_SMEM>>>(S_slots, slot_prob, slot_mask, alpha, out);
}

// round 17
// speedup vs baseline: 1.6048x; 1.0438x over previous
#include <cuda_runtime.h>
#include <cuda_fp16.h>
#include <math.h>
#include <stdint.h>

#define BB 128
#define MM 64
#define DD 512
#define KK 4096
#define CC 64

// ---------------------------------------------------------------------------
// scratch (__device__ globals per allocation-free rule)
// ---------------------------------------------------------------------------
__device__ __align__(16) __half g_Ch[KK*DD];      // C, f16, class-sorted rows
__device__ int     g_rank[KK];
__device__ uint8_t g_clsSorted[KK];
__device__ float   g_evi[BB*MM*CC];

// ---------------------------------------------------------------------------
__device__ __forceinline__ uint32_t smem_to_u32(const void* p) {
    uint32_t a;
    asm("{ .reg .u64 t; cvta.to.shared.u64 t, %1; cvt.u32.u64 %0, t; }" : "=r"(a) : "l"(p));
    return a;
}
__device__ __forceinline__ void cp16(uint32_t dst, const void* src) {
    asm volatile("cp.async.cg.shared.global [%0], [%1], 16;" :: "r"(dst), "l"(src));
}
__device__ __forceinline__ void cp_commit() { asm volatile("cp.async.commit_group;" ::: "memory"); }
__device__ __forceinline__ void cp_wait0()  { asm volatile("cp.async.wait_group 0;" ::: "memory"); }
__device__ __forceinline__ void cp_wait1()  { asm volatile("cp.async.wait_group 1;" ::: "memory"); }
__device__ __forceinline__ void cp_wait2()  { asm volatile("cp.async.wait_group 2;" ::: "memory"); }

__device__ __forceinline__ void ldm_x4(uint32_t r[4], uint32_t addr) {
    asm volatile("ldmatrix.sync.aligned.m8n8.x4.shared.b16 {%0,%1,%2,%3}, [%4];"
        : "=r"(r[0]), "=r"(r[1]), "=r"(r[2]), "=r"(r[3]) : "r"(addr));
}
__device__ __forceinline__ void mma16816(float* c, const uint32_t* a, uint32_t b0, uint32_t b1) {
    asm volatile(
        "mma.sync.aligned.m16n8k16.row.col.f32.f16.f16.f32 "
        "{%0,%1,%2,%3}, {%4,%5,%6,%7}, {%8,%9}, {%0,%1,%2,%3};"
        : "+f"(c[0]), "+f"(c[1]), "+f"(c[2]), "+f"(c[3])
        : "r"(a[0]), "r"(a[1]), "r"(a[2]), "r"(a[3]), "r"(b0), "r"(b1));
}

// full-warp reductions (32 lanes)
__device__ __forceinline__ float wsum32(float v) {
    #pragma unroll
    for (int o = 16; o > 0; o >>= 1) v += __shfl_xor_sync(0xffffffffu, v, o);
    return v;
}
__device__ __forceinline__ float wmax32(float v) {
    #pragma unroll
    for (int o = 16; o > 0; o >>= 1) v = fmaxf(v, __shfl_xor_sync(0xffffffffu, v, o));
    return v;
}

// ---------------------------------------------------------------------------
// k_perm: deterministic stable class-sort ranks (grid 64, block 256, 4-way)
// ---------------------------------------------------------------------------
__global__ void k_perm(const int* __restrict__ Ccls) {
    __shared__ int cls_s[KK];
    __shared__ int partial[64][4];
    int tid = threadIdx.x;
    for (int i = tid; i < KK; i += 256) cls_s[i] = Ccls[i] & 63;
    __syncthreads();
    int li = tid >> 2, qt = tid & 3;
    int i = blockIdx.x * 64 + li;
    int ci = cls_s[i];
    int cnt = 0;
    for (int j = qt*1024; j < qt*1024 + 1024; j++) {
        int cj = cls_s[j];
        cnt += (cj < ci) || (cj == ci && j < i);
    }
    partial[li][qt] = cnt;
    __syncthreads();
    if (qt == 0) {
        int rank = partial[li][0] + partial[li][1] + partial[li][2] + partial[li][3];
        g_rank[i] = rank;
        g_clsSorted[rank] = (uint8_t)ci;
    }
}

// prep_C: fp32 -> f16, scatter rows to class-sorted positions
__global__ void prep_C(const float* __restrict__ Cmat) {
    long i = (long)blockIdx.x * 256 + threadIdx.x;      // over float4s
    int row = (int)(i >> 7), col4 = (int)(i & 127);
    float4 v = ((const float4*)Cmat)[i];
    int r = g_rank[row];
    __half2 h0 = __floats2half2_rn(v.x, v.y);
    __half2 h1 = __floats2half2_rn(v.z, v.w);
    uint2 u; u.x = *(uint32_t*)&h0; u.y = *(uint32_t*)&h1;
    ((uint2*)(g_Ch + (size_t)r * DD))[col4] = u;
}

// ---------------------------------------------------------------------------
// K2: f16 HMMA GEMM + class exp-sum. 256 threads (8 warps), 1 CTA/SM.
// (Exact R16 configuration.)
// ---------------------------------------------------------------------------
#define THREADS 256
#define ASTR_B  1040u       // A row stride bytes (520 f16)
#define BSTR_B  80u         // B row stride bytes (40 f16, 32k chunk)
#define OFF_A   0u          // 128 x 1040 = 133120
#define OFF_B   133120u     // 8 warps x 3 stages x 2560 = 61440
#define W_BUF   7680u
#define B_STG   2560u       // 32 rows x 80
#define OFF_PART 194560u    // 2 x 128 x 8 f32 = 8192
#define SMEM_EVI 202752

__device__ __forceinline__ void load_Bwarp(uint32_t base, int half, int q,
                                           int wid, int lane) {
    const int nt = q >> 4, dc = q & 15;
    const __half* src0 = g_Ch + (size_t)(half*2048 + nt*256 + wid*32)*DD + dc*32;
    int n0 = lane >> 2, g = lane & 3;
    #pragma unroll
    for (int ii = 0; ii < 4; ii++) {
        int n = n0 + ii*8;
        cp16(base + (uint32_t)n*BSTR_B + (uint32_t)g*16, src0 + (size_t)n*DD + g*8);
    }
}

__global__ void __launch_bounds__(THREADS, 1)
k_evi(const float* __restrict__ feats) {
    extern __shared__ __align__(1024) char smem[];
    uint32_t smem_base = smem_to_u32(smem);
    const int tid = threadIdx.x, wid = tid >> 5, lane = tid & 31;
    const int bp = blockIdx.x >> 1, half = blockIdx.x & 1;

    float* part = (float*)(smem + OFF_PART);   // [2][128][8]

    const uint32_t wB = smem_base + OFF_B + (uint32_t)wid*W_BUF;

    // prime 2 stages
    load_Bwarp(wB, half, 0, wid, lane);
    cp_commit();
    load_Bwarp(wB + B_STG, half, 1, wid, lane);
    cp_commit();

    // A fill: normalize 128 rows (batches 2bp, 2bp+1) fp32 -> f16, stride 520
    {
        const float* fb = feats + (size_t)(bp*2)*MM*DD;
        for (int rr = 0; rr < 16; rr++) {
            int row = wid*16 + rr;
            const float4* rp = (const float4*)(fb + (size_t)row*DD);
            float4 v[4]; float ss = 0.f;
            #pragma unroll
            for (int u = 0; u < 4; u++) {
                v[u] = rp[lane + u*32];
                ss += v[u].x*v[u].x + v[u].y*v[u].y + v[u].z*v[u].z + v[u].w*v[u].w;
            }
            ss = wsum32(ss);
            float inv = 1.0f / fmaxf(sqrtf(ss), 1e-12f);
            #pragma unroll
            for (int u = 0; u < 4; u++) {
                __half2 h0 = __floats2half2_rn(v[u].x*inv, v[u].y*inv);
                __half2 h1 = __floats2half2_rn(v[u].z*inv, v[u].w*inv);
                uint2 w; w.x = *(uint32_t*)&h0; w.y = *(uint32_t*)&h1;
                *(uint2*)(smem + OFF_A + (uint32_t)row*ASTR_B + (uint32_t)(lane + u*32)*8) = w;
            }
        }
    }
    __syncthreads();    // A visible to all warps

    const uint32_t aBase = smem_base + OFF_A
        + (uint32_t)(lane & 15)*ASTR_B + (uint32_t)(lane >> 4)*16;
    const uint32_t bLane = (uint32_t)((lane & 7) + ((lane >> 4) << 3))*BSTR_B
        + (uint32_t)((lane >> 3) & 1)*16;

    float acc[8][4][4];
    int bufsel = 0;

    #pragma unroll 1
    for (int q = 0; q < 128; ++q) {
        const int nt = q >> 4, dc = q & 15;

        if (q + 2 < 128) {
            int nb = bufsel + 2; if (nb >= 3) nb -= 3;
            load_Bwarp(wB + (uint32_t)nb*B_STG, half, q + 2, wid, lane);
            cp_commit();
            cp_wait2();
        } else if (q + 1 < 128) {
            cp_wait1();
        } else {
            cp_wait0();
        }
        __syncwarp();

        if (dc == 0) {
            #pragma unroll
            for (int i = 0; i < 8; i++)
                #pragma unroll
                for (int j = 0; j < 4; j++)
                    #pragma unroll
                    for (int v = 0; v < 4; v++) acc[i][j][v] = 0.f;
        }

        const uint32_t bBuf = wB + (uint32_t)bufsel*B_STG + bLane;
        #pragma unroll
        for (int ks = 0; ks < 2; ++ks) {
            uint32_t kb = (uint32_t)(dc*32 + ks*16)*2;
            uint32_t a[8][4];
            #pragma unroll
            for (int i = 0; i < 8; i++) ldm_x4(a[i], aBase + (uint32_t)(i*16)*ASTR_B + kb);
            uint32_t bf[2][4];
            uint32_t bAddr = bBuf + (uint32_t)ks*32;
            ldm_x4(bf[0], bAddr);
            ldm_x4(bf[1], bAddr + 16*BSTR_B);
            #pragma unroll
            for (int i = 0; i < 8; i++) {
                mma16816(acc[i][0], a[i], bf[0][0], bf[0][1]);
                mma16816(acc[i][1], a[i], bf[0][2], bf[0][3]);
                mma16816(acc[i][2], a[i], bf[1][0], bf[1][1]);
                mma16816(acc[i][3], a[i], bf[1][2], bf[1][3]);
            }
        }

        if (dc == 15) {
            float* pb = part + (nt & 1)*128*8;
            #pragma unroll
            for (int i = 0; i < 8; i++) {
                #pragma unroll
                for (int h = 0; h < 2; h++) {
                    float s = 0.f;
                    #pragma unroll
                    for (int j = 0; j < 4; j++) {
                        s += __expf(2.0f * acc[i][j][h*2 + 0]);
                        s += __expf(2.0f * acc[i][j][h*2 + 1]);
                    }
                    s += __shfl_xor_sync(0xffffffffu, s, 1);
                    s += __shfl_xor_sync(0xffffffffu, s, 2);
                    if ((lane & 3) == 0) {
                        int row = i*16 + h*8 + (lane >> 2);
                        pb[row*8 + wid] = s;
                    }
                }
            }
            __syncthreads();
            {
                int row = tid >> 1, cg = tid & 1;
                int batch = bp*2 + (row >> 6), slot = row & 63;
                float* dst = g_evi + ((size_t)batch*MM + slot)*CC;
                #pragma unroll
                for (int cj = 0; cj < 2; ++cj) {
                    int ci = cg*2 + cj;
                    float s = pb[row*8 + ci*2] + pb[row*8 + ci*2 + 1];
                    int c = (int)g_clsSorted[half*2048 + nt*256 + ci*64];
                    dst[c] = 0.5f * logf(fmaxf(s, 1e-8f));
                }
            }
        }
        if (++bufsel == 3) bufsel = 0;
    }
}

// ---------------------------------------------------------------------------
// K3: fused epilogue. Warp-0 weights overlap + 4-row-batched S normalize.
// ---------------------------------------------------------------------------
#define KO_S    0u          // S_norm f16 [64][520] = 66560
#define KO_G    66560u      // gathered top1 rows f16 [64][520] = 66560
#define KO_EVI  133120u     // f32 [4096] = 16384
#define KO_SUP  149504u     // f32 [64][68] = 17408
#define KO_W    166912u     // f32 [64]
#define KO_LP   167168u
#define KO_T1V  167424u
#define KO_T1I  167680u     // int [64]
#define KO_SMEM 167936

// normalize 4 consecutive rows with batched loads (MLP 16 per thread)
__device__ __forceinline__ void norm_rows4(const float* sb, char* smem, int row0, int lane) {
    float4 v[4][4];
    #pragma unroll
    for (int r = 0; r < 4; r++) {
        const float4* rp = (const float4*)(sb + (size_t)(row0 + r)*DD);
        #pragma unroll
        for (int u = 0; u < 4; u++) v[r][u] = rp[lane + u*32];
    }
    #pragma unroll
    for (int r = 0; r < 4; r++) {
        float ss = 0.f;
        #pragma unroll
        for (int u = 0; u < 4; u++)
            ss += v[r][u].x*v[r][u].x + v[r][u].y*v[r][u].y
                + v[r][u].z*v[r][u].z + v[r][u].w*v[r][u].w;
        ss = wsum32(ss);
        float inv = 1.0f / fmaxf(sqrtf(ss), 1e-12f);
        #pragma unroll
        for (int u = 0; u < 4; u++) {
            __half2 h0 = __floats2half2_rn(v[r][u].x*inv, v[r][u].y*inv);
            __half2 h1 = __floats2half2_rn(v[r][u].z*inv, v[r][u].w*inv);
            uint2 wv; wv.x = *(uint32_t*)&h0; wv.y = *(uint32_t*)&h1;
            *(uint2*)(smem + KO_S + (uint32_t)(row0 + r)*ASTR_B + (uint32_t)(lane + u*32)*8) = wv;
        }
    }
}

__global__ void __launch_bounds__(256, 1)
k_out(const float* __restrict__ S_slots,
      const float* __restrict__ slot_prob,
      const float* __restrict__ slot_mask,
      const float* __restrict__ alpha,
      float* __restrict__ out) {
    extern __shared__ __align__(1024) char smem[];
    uint32_t smem_base = smem_to_u32(smem);
    float* evi_s = (float*)(smem + KO_EVI);
    float* sup_s = (float*)(smem + KO_SUP);
    float* w_s   = (float*)(smem + KO_W);
    float* lp_s  = (float*)(smem + KO_LP);
    float* t1v   = (float*)(smem + KO_T1V);
    int*   t1i   = (int*)(smem + KO_T1I);

    int b = blockIdx.x, tid = threadIdx.x;
    int wid = tid >> 5, lane = tid & 31;
    const float* sb = S_slots + (size_t)b*MM*DD;

    if (wid == 0) {
        // ---- warp-0-only soft-topk weights + log(P_sup), barrier-free ----
        int m0 = lane, m1 = lane + 32;
        float mk0 = slot_mask[m0], mk1 = slot_mask[m1];
        float pv0 = slot_prob[b*MM + m0] * mk0;
        float pv1 = slot_prob[b*MM + m1] * mk1;
        float v0 = pv0, v1 = pv1;
        int top0, top1, top2;
        #pragma unroll
        for (int t = 0; t < 3; t++) {
            float bv = v0; int bi = m0;
            if (v1 > bv) { bv = v1; bi = m1; }
            #pragma unroll
            for (int o = 16; o > 0; o >>= 1) {
                float ov = __shfl_xor_sync(0xffffffffu, bv, o);
                int   oi = __shfl_xor_sync(0xffffffffu, bi, o);
                if (ov > bv || (ov == bv && oi < bi)) { bv = ov; bi = oi; }
            }
            int bb = __shfl_sync(0xffffffffu, bi, 0);
            if (t == 0) top0 = bb; else if (t == 1) top1 = bb; else top2 = bb;
            if (m0 == bb) v0 = -INFINITY;
            if (m1 == bb) v1 = -INFINITY;
        }
        float k0 = (m0 == top0 || m0 == top1 || m0 == top2) ? 1.f : 0.f;
        float k1 = (m1 == top0 || m1 == top1 || m1 == top2) ? 1.f : 0.f;
        float q0 = pv0 * k0, q1 = pv1 * k1;
        float mean = wsum32(q0 + q1) * (1.0f/64.0f);
        float z0 = (q0 - mean) * 2.0f, z1 = (q1 - mean) * 2.0f;
        float zmax = wmax32(fmaxf(z0, z1));
        float e0 = expf(z0 - zmax), e1 = expf(z1 - zmax);
        float zsum = wsum32(e0 + e1);
        float w0 = (e0 / zsum) * mk0, w1 = (e1 / zsum) * mk1;
        float wsum = wsum32(w0 + w1);
        float inw = 1.0f / fmaxf(wsum, 1e-8f);
        w0 *= inw; w1 *= inw;
        w_s[m0] = w0; w_s[m1] = w1;
        float t0 = logf(w0 + 1e-8f) * (1.0f/1.6f);
        float t1 = logf(w1 + 1e-8f) * (1.0f/1.6f);
        float tmax = wmax32(fmaxf(t0, t1));
        float et0 = expf(t0 - tmax), et1 = expf(t1 - tmax);
        float lts = logf(wsum32(et0 + et1));
        lp_s[m0] = fmaxf(t0 - tmax - lts, -18.420680744f);
        lp_s[m1] = fmaxf(t1 - tmax - lts, -18.420680744f);
        // then normalize S rows 56..63
        norm_rows4(sb, smem, 56, lane);
        norm_rows4(sb, smem, 60, lane);
    } else {
        // ---- warps 1-7: load evi (float4) + normalize S rows 0..55 ----
        const float4* esrc = (const float4*)(g_evi + (size_t)b*MM*CC);
        float4* edst = (float4*)evi_s;
        for (int i = tid - 32; i < MM*CC/4; i += 224) edst[i] = esrc[i];
        int r0 = (wid - 1) * 8;
        norm_rows4(sb, smem, r0, lane);
        norm_rows4(sb, smem, r0 + 4, lane);
    }
    __syncthreads();

    // top1 over slots per class: 4 threads per class, 16 m each, shfl combine
    {
        int c = tid >> 2, q4 = tid & 3;
        float best = -INFINITY; int bi = 0;
        #pragma unroll 4
        for (int k = 0; k < 16; k++) {
            int mm = q4*16 + k;
            float scv = evi_s[mm*CC + c] * w_s[mm];
            if (scv > best) { best = scv; bi = mm; }
        }
        #pragma unroll
        for (int o = 1; o < 4; o <<= 1) {
            float ov = __shfl_xor_sync(0xffffffffu, best, o);
            int   oi = __shfl_xor_sync(0xffffffffu, bi, o);
            if (ov > best || (ov == best && oi < bi)) { best = ov; bi = oi; }
        }
        if (q4 == 0) { t1v[c] = best; t1i[c] = bi; }
    }
    __syncthreads();

    // gather top1 rows: G[c] = S_norm[t1i[c]]
    {
        int c = tid >> 2, q4 = tid & 3;
        int src = t1i[c];
        const uint4* sp = (const uint4*)(smem + KO_S + (uint32_t)src*ASTR_B);
        uint4* gp = (uint4*)(smem + KO_G + (uint32_t)c*ASTR_B);
        for (int k = q4; k < 65; k += 4) gp[k] = sp[k];
    }
    __syncthreads();

    // cos GEMM 64x64x512 via HMMA: warps 2(m) x 4(n), warp tile 32m x 16n
    {
        int wr = wid & 1, wc = wid >> 1;
        const uint32_t aBase = smem_base + KO_S
            + (uint32_t)(wr*32 + (lane & 15))*ASTR_B + (uint32_t)(lane >> 4)*16;
        const uint32_t bBase = smem_base + KO_G
            + (uint32_t)(wc*16 + (lane & 7) + ((lane >> 4) << 3))*ASTR_B
            + (uint32_t)((lane >> 3) & 1)*16;
        float acc[2][2][4];
        #pragma unroll
        for (int i = 0; i < 2; i++)
            #pragma unroll
            for (int j = 0; j < 2; j++)
                #pragma unroll
                for (int v = 0; v < 4; v++) acc[i][j][v] = 0.f;
        #pragma unroll 4
        for (int ks = 0; ks < 32; ++ks) {
            uint32_t kb = (uint32_t)ks*32;
            uint32_t a0[4], a1[4], bf[4];
            ldm_x4(a0, aBase + kb);
            ldm_x4(a1, aBase + 16*ASTR_B + kb);
            ldm_x4(bf, bBase + kb);
            mma16816(acc[0][0], a0, bf[0], bf[1]);
            mma16816(acc[0][1], a0, bf[2], bf[3]);
            mma16816(acc[1][0], a1, bf[0], bf[1]);
            mma16816(acc[1][1], a1, bf[2], bf[3]);
        }
        #pragma unroll
        for (int i = 0; i < 2; i++) {
            #pragma unroll
            for (int jj = 0; jj < 2; jj++) {
                int mB = wr*32 + i*16 + (lane >> 2);
                int c0 = wc*16 + jj*8 + (lane & 3)*2;
                #pragma unroll
                for (int v = 0; v < 4; v++) {
                    int mm = mB + (v >> 1)*8;
                    int c = c0 + (v & 1);
                    float cosv = fmaxf(acc[i][jj][v], 0.f);
                    float sr = evi_s[mm*CC + c] + lp_s[mm] - cosv;
                    if (mm == t1i[c]) sr = -10000.0f;
                    sup_s[mm*68 + c] = sr;
                }
            }
        }
    }
    __syncthreads();

    // support LSE: 4 threads per class, shfl combine
    {
        int c = tid >> 2, q4 = tid & 3;
        float mx = -INFINITY;
        #pragma unroll 4
        for (int k = 0; k < 16; k++) mx = fmaxf(mx, sup_s[(q4*16 + k)*68 + c]);
        #pragma unroll
        for (int o = 1; o < 4; o <<= 1) mx = fmaxf(mx, __shfl_xor_sync(0xffffffffu, mx, o));
        float sum = 0.f;
        #pragma unroll 4
        for (int k = 0; k < 16; k++) sum += expf(sup_s[(q4*16 + k)*68 + c] - mx);
        #pragma unroll
        for (int o = 1; o < 4; o <<= 1) sum += __shfl_xor_sync(0xffffffffu, sum, o);
        if (q4 == 0) {
            float sval = mx + logf(sum);
            out[b*CC + c] = alpha[0] * (t1v[c] + 0.4f * sval);
        }
    }
}

// ---------------------------------------------------------------------------
extern "C" void kernel_launch(void* const* d_in, const int* in_sizes, int n_in,
                              void* d_out, int out_size) {
    const float* feats     = (const float*)d_in[0];
    const float* slot_prob = (const float*)d_in[1];
    const float* slot_mask = (const float*)d_in[2];
    const float* S_slots   = (const float*)d_in[3];
    const float* Cmat      = (const float*)d_in[4];
    const int*   Ccls      = (const int*)d_in[5];
    const float* alpha     = (const float*)d_in[6];
    float* out = (float*)d_out;

    cudaFuncSetAttribute(k_evi, cudaFuncAttributeMaxDynamicSharedMemorySize, SMEM_EVI);
    cudaFuncSetAttribute(k_out, cudaFuncAttributeMaxDynamicSharedMemorySize, KO_SMEM);

    k_perm<<<KK/64, 256>>>(Ccls);
    prep_C<<<KK*DD/1024, 256>>>(Cmat);
    k_evi<<<BB, THREADS, SMEM_EVI>>>(feats);
    k_out<<<BB, 256, KO_SMEM>>>(S_slots, slot_prob, slot_mask, alpha, out);
}